// round 5
// baseline (speedup 1.0000x reference)
#include <cuda_runtime.h>
#include <cstdint>

#define Bsz   8
#define Cch   192
#define Himg  224
#define Wimg  224
#define Pw    7
#define NHEAD 6
#define HDIM  32
#define WGRID 32
#define NWIN  1024
#define PPp   49
#define Mrows 401408
#define HWSZ  50176

typedef unsigned long long u64t;

static __device__ float g_xw[(size_t)Mrows * Cch];
static __device__ float g_qkv[(size_t)Mrows * 3 * Cch];
static __device__ float g_attn[(size_t)Mrows * Cch];
static __device__ float g_out2[(size_t)Mrows * Cch];
static __device__ float g_wqkv[576 * 192];
static __device__ float g_wout[192 * 192];

// ───────────────────────── helpers ─────────────────────────
__device__ __forceinline__ uint32_t f2tf(float f) {
    uint32_t u;
    asm("cvt.rna.tf32.f32 %0, %1;" : "=r"(u) : "f"(f));
    return u;
}
__device__ __forceinline__ float f2tf_f(float f) { return __uint_as_float(f2tf(f)); }
__device__ __forceinline__ u64t fma2(u64t a, u64t b, u64t c) {
    u64t d;
    asm("fma.rn.f32x2 %0, %1, %2, %3;" : "=l"(d) : "l"(a), "l"(b), "l"(c));
    return d;
}
__device__ __forceinline__ void mma_m16n8k8(float* c, const uint32_t* a, const uint32_t* b) {
    asm volatile(
        "mma.sync.aligned.m16n8k8.row.col.f32.tf32.tf32.f32 "
        "{%0,%1,%2,%3}, {%4,%5,%6,%7}, {%8,%9}, {%0,%1,%2,%3};"
        : "+f"(c[0]), "+f"(c[1]), "+f"(c[2]), "+f"(c[3])
        : "r"(a[0]), "r"(a[1]), "r"(a[2]), "r"(a[3]), "r"(b[0]), "r"(b[1]));
}
__device__ __forceinline__ void cp16(uint32_t dst, const float* src) {
    asm volatile("cp.async.cg.shared.global [%0], [%1], 16;" :: "r"(dst), "l"(src));
}
#define CP_COMMIT() asm volatile("cp.async.commit_group;" ::: "memory")
#define CP_WAIT(n)  asm volatile("cp.async.wait_group %0;" :: "n"(n) : "memory")

__global__ void k_round(const float* __restrict__ w, float* __restrict__ o, int n) {
    int i = blockIdx.x * 256 + threadIdx.x;
    if (i < n) o[i] = f2tf_f(w[i]);
}

// ───────────────────────── transposes ─────────────────────────
__device__ __forceinline__ int m_of(int b, int hw) {
    int h = hw / Wimg;
    int w = hw - h * Wimg;
    int wi = h / Pw, pi = h - wi * Pw;
    int wj = w / Pw, pj = w - wj * Pw;
    return ((b * WGRID + wi) * WGRID + wj) * PPp + pi * Pw + pj;
}

__global__ void k_gather(const float* __restrict__ x, float* __restrict__ xw) {
    __shared__ float tile[32][33];
    int hw0 = blockIdx.x << 5, c0 = blockIdx.y << 5, b = blockIdx.z;
    int tx = threadIdx.x, ty = threadIdx.y;
    const float* xb = x + (size_t)b * Cch * HWSZ;
#pragma unroll
    for (int it = 0; it < 4; it++) {
        int c = c0 + ty + it * 8;
        tile[ty + it * 8][tx] = xb[(size_t)c * HWSZ + hw0 + tx];
    }
    __syncthreads();
#pragma unroll
    for (int it = 0; it < 4; it++) {
        int hw = hw0 + ty + it * 8;
        int m = m_of(b, hw);
        xw[(size_t)m * Cch + c0 + tx] = f2tf_f(tile[tx][ty + it * 8]);
    }
}

__global__ void k_scatter(const float* __restrict__ out2, float* __restrict__ out) {
    __shared__ float tile[32][33];
    int hw0 = blockIdx.x << 5, c0 = blockIdx.y << 5, b = blockIdx.z;
    int tx = threadIdx.x, ty = threadIdx.y;
#pragma unroll
    for (int it = 0; it < 4; it++) {
        int hw = hw0 + ty + it * 8;
        int m = m_of(b, hw);
        tile[ty + it * 8][tx] = out2[(size_t)m * Cch + c0 + tx];
    }
    __syncthreads();
    float* ob = out + (size_t)b * Cch * HWSZ;
#pragma unroll
    for (int it = 0; it < 4; it++) {
        int c = c0 + ty + it * 8;
        ob[(size_t)c * HWSZ + hw0 + tx] = tile[tx][ty + it * 8];
    }
}

// ───────────────────────── TF32 mma.sync GEMM v2 ─────────────────────────
// BM=256, BN=64, BK=16, 3-stage cp.async, 256 threads, warp tile 64x32.
#define GBM 256
#define GBN 64
#define GBK 16
#define KTOT 192
#define KTILES 12
#define GSTG 3
#define ASTR 20
#define A_FL (GBM * ASTR)            // 5120 floats
#define B_FL (GBN * ASTR)            // 1280 floats
#define STG_FL (A_FL + B_FL)         // 6400 floats
#define GEMM_SMEM (GSTG * STG_FL * 4)

__global__ void __launch_bounds__(256, 2)
k_gemm_mma(const float* __restrict__ A, const float* __restrict__ Wt,
           const float* __restrict__ bias, float* __restrict__ C, int Ntot) {
    extern __shared__ float smf[];

    int tid = threadIdx.x;
    int wid = tid >> 5, lane = tid & 31;
    int gp = lane >> 2, tg = lane & 3;
    int wm = wid & 3, wn = wid >> 2;       // 4(M) x 2(N)
    size_t bm = (size_t)blockIdx.y * GBM;
    int bn = blockIdx.x * GBN;

    int lr = tid >> 2, lq = tid & 3;       // load row / k-quarter

    const float* Ag[4];
#pragma unroll
    for (int j = 0; j < 4; j++) Ag[j] = A + (bm + lr + 64 * j) * KTOT + lq * 4;
    const float* Bg = Wt + (size_t)(bn + lr) * KTOT + lq * 4;

    uint32_t smb = (uint32_t)__cvta_generic_to_shared(smf);
    uint32_t aw[4], bw;
#pragma unroll
    for (int j = 0; j < 4; j++) aw[j] = smb + ((lr + 64 * j) * ASTR + lq * 4) * 4;
    bw = smb + (A_FL + lr * ASTR + lq * 4) * 4;

    float acc[4][4][4];
#pragma unroll
    for (int mt = 0; mt < 4; mt++)
#pragma unroll
        for (int nt = 0; nt < 4; nt++)
#pragma unroll
            for (int r = 0; r < 4; r++) acc[mt][nt][r] = 0.f;

    // prologue: tiles 0,1 -> stages 0,1
#pragma unroll
    for (int t = 0; t < 2; t++) {
        uint32_t so = t * (STG_FL * 4);
#pragma unroll
        for (int j = 0; j < 4; j++) cp16(aw[j] + so, Ag[j] + t * GBK);
        cp16(bw + so, Bg + t * GBK);
        CP_COMMIT();
    }

    const float* as_w = smf + (wm * 64 + gp) * ASTR + tg;
    const float* bs_w = smf + A_FL + (wn * 32 + gp) * ASTR + tg;

#pragma unroll 1
    for (int t = 0; t < KTILES; t++) {
        if (t < KTILES - 1) { CP_WAIT(1); } else { CP_WAIT(0); }
        __syncthreads();

        int st = t % GSTG;
        const float* as = as_w + st * STG_FL;
        const float* bs = bs_w + st * STG_FL;
#pragma unroll
        for (int ks = 0; ks < 2; ks++) {
            uint32_t a[4][4], b[4][2];
#pragma unroll
            for (int mt = 0; mt < 4; mt++) {
                const float* p = as + mt * 16 * ASTR + ks * 8;
                a[mt][0] = __float_as_uint(p[0]);
                a[mt][1] = __float_as_uint(p[8 * ASTR]);
                a[mt][2] = __float_as_uint(p[4]);
                a[mt][3] = __float_as_uint(p[8 * ASTR + 4]);
            }
#pragma unroll
            for (int nt = 0; nt < 4; nt++) {
                const float* p = bs + nt * 8 * ASTR + ks * 8;
                b[nt][0] = __float_as_uint(p[0]);
                b[nt][1] = __float_as_uint(p[4]);
            }
#pragma unroll
            for (int mt = 0; mt < 4; mt++)
#pragma unroll
                for (int nt = 0; nt < 4; nt++)
                    mma_m16n8k8(acc[mt][nt], a[mt], b[nt]);
        }

        // prefetch tile t+2 -> stage (t+2)%3 (safe: sync above separated prior readers)
        if (t + 2 < KTILES) {
            int tt = t + 2;
            uint32_t so = (tt % GSTG) * (STG_FL * 4);
#pragma unroll
            for (int j = 0; j < 4; j++) cp16(aw[j] + so, Ag[j] + tt * GBK);
            cp16(bw + so, Bg + tt * GBK);
            CP_COMMIT();
        } else {
            CP_COMMIT();   // keep group accounting uniform
        }
    }

#pragma unroll
    for (int mt = 0; mt < 4; mt++) {
        int row = (int)bm + wm * 64 + mt * 16 + gp;
#pragma unroll
        for (int nt = 0; nt < 4; nt++) {
            int col = bn + wn * 32 + nt * 8 + tg * 2;
            float b0 = bias[col], b1 = bias[col + 1];
            float2 v0 = make_float2(acc[mt][nt][0] + b0, acc[mt][nt][1] + b1);
            float2 v1 = make_float2(acc[mt][nt][2] + b0, acc[mt][nt][3] + b1);
            *(float2*)(C + (size_t)row * Ntot + col) = v0;
            *(float2*)(C + (size_t)(row + 8) * Ntot + col) = v1;
        }
    }
}

// ─────────────────── attention v3: two-pass, low-reg ───────────────────
__global__ void __launch_bounds__(64)
k_attn(const float* __restrict__ qkv, float* __restrict__ attn,
       const float* __restrict__ rel_pos) {
    int blk = blockIdx.x;
    int head = blk % NHEAD;
    int win = blk / NHEAD;
    int base = win * PPp;
    int tid = threadIdx.x;

    __shared__ __align__(16) float ks[PPp * HDIM];
    __shared__ __align__(16) float vs[PPp * HDIM];
    __shared__ float sb[169];

    const size_t rowb = (size_t)base * 576;
    int toff = head * HDIM;

    // coalesced float4 loads of K and V
    for (int idx = tid; idx < PPp * 8; idx += 64) {
        int r = idx >> 3, d4 = (idx & 7) * 4;
        size_t g = rowb + (size_t)r * 576 + toff + d4;
        *(float4*)&ks[r * HDIM + d4] = *(const float4*)&qkv[g + 192];
        *(float4*)&vs[r * HDIM + d4] = *(const float4*)&qkv[g + 384];
    }
    for (int idx = tid; idx < 169; idx += 64) sb[idx] = rel_pos[head * 169 + idx];
    __syncthreads();

    int i = tid;
    if (i >= PPp) return;

    // q row in registers (direct from gmem)
    u64t q2[16];
    {
        const u64t* qp = (const u64t*)(qkv + rowb + (size_t)i * 576 + toff);
#pragma unroll
        for (int t = 0; t < 16; t++) q2[t] = qp[t];
    }
    int ii = i / 7, ij = i - (i / 7) * 7;
    const float scale = 0.17677669529663687f;

    // pass 1: row max
    float mx = -1e30f;
#pragma unroll
    for (int j1 = 0; j1 < 7; j1++) {
        int ri = (ii - j1 + 6) * 13 + ij + 6;
#pragma unroll
        for (int j2 = 0; j2 < 7; j2++) {
            int j = j1 * 7 + j2;
            const u64t* kp = (const u64t*)(ks + j * HDIM);
            u64t acc2 = 0ull;
#pragma unroll
            for (int t = 0; t < 16; t++) acc2 = fma2(q2[t], kp[t], acc2);
            float s = (__uint_as_float((uint32_t)acc2) +
                       __uint_as_float((uint32_t)(acc2 >> 32))) * scale + sb[ri - j2];
            mx = fmaxf(mx, s);
        }
    }

    // pass 2: exp, sum, accumulate
    u64t o2[16];
#pragma unroll
    for (int t = 0; t < 16; t++) o2[t] = 0ull;
    float sum = 0.f;
#pragma unroll
    for (int j1 = 0; j1 < 7; j1++) {
        int ri = (ii - j1 + 6) * 13 + ij + 6;
#pragma unroll
        for (int j2 = 0; j2 < 7; j2++) {
            int j = j1 * 7 + j2;
            const u64t* kp = (const u64t*)(ks + j * HDIM);
            u64t acc2 = 0ull;
#pragma unroll
            for (int t = 0; t < 16; t++) acc2 = fma2(q2[t], kp[t], acc2);
            float s = (__uint_as_float((uint32_t)acc2) +
                       __uint_as_float((uint32_t)(acc2 >> 32))) * scale + sb[ri - j2];
            float e = __expf(s - mx);
            sum += e;
            u64t p2;
            uint32_t pb = __float_as_uint(e);
            asm("mov.b64 %0, {%1, %1};" : "=l"(p2) : "r"(pb));
            const u64t* vp = (const u64t*)(vs + j * HDIM);
#pragma unroll
            for (int t = 0; t < 16; t++) o2[t] = fma2(p2, vp[t], o2[t]);
        }
    }
    float inv = 1.f / sum;

    float* op = attn + (size_t)(base + i) * Cch + toff;
#pragma unroll
    for (int t = 0; t < 16; t++) {
        float lo = __uint_as_float((uint32_t)o2[t]) * inv;
        float hi = __uint_as_float((uint32_t)(o2[t] >> 32)) * inv;
        *(float2*)(op + t * 2) = make_float2(f2tf_f(lo), f2tf_f(hi));
    }
}

// ───────────────────────── launch ─────────────────────────
extern "C" void kernel_launch(void* const* d_in, const int* in_sizes, int n_in,
                              void* d_out, int out_size) {
    const float* x       = (const float*)d_in[0];
    const float* w_qkv   = (const float*)d_in[1];
    const float* b_qkv   = (const float*)d_in[2];
    const float* rel_pos = (const float*)d_in[3];
    const float* w_out   = (const float*)d_in[4];
    const float* b_out   = (const float*)d_in[5];
    float* out = (float*)d_out;

    float *p_xw, *p_qkv, *p_attn, *p_out2, *p_wqkv, *p_wout;
    cudaGetSymbolAddress((void**)&p_xw, g_xw);
    cudaGetSymbolAddress((void**)&p_qkv, g_qkv);
    cudaGetSymbolAddress((void**)&p_attn, g_attn);
    cudaGetSymbolAddress((void**)&p_out2, g_out2);
    cudaGetSymbolAddress((void**)&p_wqkv, g_wqkv);
    cudaGetSymbolAddress((void**)&p_wout, g_wout);

    cudaFuncSetAttribute(k_gemm_mma, cudaFuncAttributeMaxDynamicSharedMemorySize, GEMM_SMEM);

    k_round<<<(576 * 192 + 255) / 256, 256>>>(w_qkv, p_wqkv, 576 * 192);
    k_round<<<(192 * 192 + 255) / 256, 256>>>(w_out, p_wout, 192 * 192);

    dim3 tb(32, 8);
    dim3 tg(HWSZ / 32, Cch / 32, Bsz);
    k_gather<<<tg, tb>>>(x, p_xw);
    k_gemm_mma<<<dim3(576 / GBN, Mrows / GBM), 256, GEMM_SMEM>>>(p_xw, p_wqkv, b_qkv, p_qkv, 576);
    k_attn<<<(Mrows / PPp) * NHEAD, 64>>>(p_qkv, p_attn, rel_pos);
    k_gemm_mma<<<dim3(192 / GBN, Mrows / GBM), 256, GEMM_SMEM>>>(p_attn, p_wout, b_out, p_out2, 192);
    k_scatter<<<tg, tb>>>(p_out2, out);
}

// round 6
// speedup vs baseline: 1.0833x; 1.0833x over previous
#include <cuda_runtime.h>
#include <cstdint>

#define Bsz   8
#define Cch   192
#define Himg  224
#define Wimg  224
#define Pw    7
#define NHEAD 6
#define HDIM  32
#define WGRID 32
#define NWIN  1024
#define PPp   49
#define Mrows 401408
#define HWSZ  50176

typedef unsigned long long u64t;

static __device__ float g_xw[(size_t)Mrows * Cch];
static __device__ float g_qkv[(size_t)Mrows * 3 * Cch];
static __device__ float g_attn[(size_t)Mrows * Cch];
static __device__ float g_out2[(size_t)Mrows * Cch];
static __device__ float g_wqkv[576 * 192];
static __device__ float g_wout[192 * 192];

// k-permutation within groups of 8: pos = 2*(k&3) + ((k>>2)&1)
__device__ __forceinline__ int kperm(int c) {
    return (c & ~7) | (((c & 3) << 1) | ((c >> 2) & 1));
}

// ───────────────────────── helpers ─────────────────────────
__device__ __forceinline__ uint32_t f2tf(float f) {
    uint32_t u;
    asm("cvt.rna.tf32.f32 %0, %1;" : "=r"(u) : "f"(f));
    return u;
}
__device__ __forceinline__ float f2tf_f(float f) { return __uint_as_float(f2tf(f)); }
__device__ __forceinline__ u64t fma2(u64t a, u64t b, u64t c) {
    u64t d;
    asm("fma.rn.f32x2 %0, %1, %2, %3;" : "=l"(d) : "l"(a), "l"(b), "l"(c));
    return d;
}
__device__ __forceinline__ void mma_m16n8k8(float* c, const uint32_t* a, const uint32_t* b) {
    asm volatile(
        "mma.sync.aligned.m16n8k8.row.col.f32.tf32.tf32.f32 "
        "{%0,%1,%2,%3}, {%4,%5,%6,%7}, {%8,%9}, {%0,%1,%2,%3};"
        : "+f"(c[0]), "+f"(c[1]), "+f"(c[2]), "+f"(c[3])
        : "r"(a[0]), "r"(a[1]), "r"(a[2]), "r"(a[3]), "r"(b[0]), "r"(b[1]));
}
__device__ __forceinline__ void cp16(uint32_t dst, const float* src) {
    asm volatile("cp.async.cg.shared.global [%0], [%1], 16;" :: "r"(dst), "l"(src));
}
#define CP_COMMIT() asm volatile("cp.async.commit_group;" ::: "memory")
#define CP_WAIT(n)  asm volatile("cp.async.wait_group %0;" :: "n"(n) : "memory")

__global__ void k_round(const float* __restrict__ w, float* __restrict__ o, int n) {
    int i = blockIdx.x * 256 + threadIdx.x;
    if (i < n) {
        int row = i / 192, k = i - row * 192;
        o[row * 192 + kperm(k)] = f2tf_f(w[i]);
    }
}

// ───────────────────────── transposes ─────────────────────────
__device__ __forceinline__ int m_of(int b, int hw) {
    int h = hw / Wimg;
    int w = hw - h * Wimg;
    int wi = h / Pw, pi = h - wi * Pw;
    int wj = w / Pw, pj = w - wj * Pw;
    return ((b * WGRID + wi) * WGRID + wj) * PPp + pi * Pw + pj;
}

__global__ void k_gather(const float* __restrict__ x, float* __restrict__ xw) {
    __shared__ float tile[32][33];
    int hw0 = blockIdx.x << 5, c0 = blockIdx.y << 5, b = blockIdx.z;
    int tx = threadIdx.x, ty = threadIdx.y;
    const float* xb = x + (size_t)b * Cch * HWSZ;
#pragma unroll
    for (int it = 0; it < 4; it++) {
        int c = c0 + ty + it * 8;
        tile[ty + it * 8][tx] = xb[(size_t)c * HWSZ + hw0 + tx];
    }
    __syncthreads();
    int cp = kperm(c0 + tx);   // permuted channel position
#pragma unroll
    for (int it = 0; it < 4; it++) {
        int hw = hw0 + ty + it * 8;
        int m = m_of(b, hw);
        xw[(size_t)m * Cch + cp] = f2tf_f(tile[tx][ty + it * 8]);
    }
}

__global__ void k_scatter(const float* __restrict__ out2, float* __restrict__ out) {
    __shared__ float tile[32][33];
    int hw0 = blockIdx.x << 5, c0 = blockIdx.y << 5, b = blockIdx.z;
    int tx = threadIdx.x, ty = threadIdx.y;
#pragma unroll
    for (int it = 0; it < 4; it++) {
        int hw = hw0 + ty + it * 8;
        int m = m_of(b, hw);
        tile[ty + it * 8][tx] = out2[(size_t)m * Cch + c0 + tx];
    }
    __syncthreads();
    float* ob = out + (size_t)b * Cch * HWSZ;
#pragma unroll
    for (int it = 0; it < 4; it++) {
        int c = c0 + ty + it * 8;
        ob[(size_t)c * HWSZ + hw0 + tx] = tile[tx][ty + it * 8];
    }
}

// ───────────────── TF32 GEMM v3: A-resident, paired-k LDS.64 ─────────────────
// BM=128, full K=192 A panel resident; n-loop inside block; B streamed in
// 64x96 chunks (3 buffers). Operands tf32-rounded AND k-permuted in memory.
#define GBM 128
#define GBN 64
#define KTOT 192
#define KH 96                 // half-k chunk
#define ASTRIDE 200           // floats per A row in smem
#define BSTRIDE 104           // floats per B chunk row in smem
#define A_FL (GBM * ASTRIDE)          // 25600 floats
#define B_FL (GBN * BSTRIDE)          // 6656 floats
#define GEMM_SMEM ((A_FL + 3 * B_FL) * 4)

__global__ void __launch_bounds__(256, 1)
k_gemm_mma(const float* __restrict__ A, const float* __restrict__ Wt,
           const float* __restrict__ bias, float* __restrict__ C,
           int Ntot, int NT) {
    extern __shared__ float smf[];
    float* Asm = smf;
    float* Bsm = smf + A_FL;

    int tid = threadIdx.x;
    int wid = tid >> 5, lane = tid & 31;
    int gp = lane >> 2, tg = lane & 3;
    int wm = wid & 3, wn = wid >> 2;        // 4(M) x 2(N), warptile 32x32
    size_t bm = (size_t)blockIdx.x * GBM;

    uint32_t smb = (uint32_t)__cvta_generic_to_shared(smf);
    const int NCHUNK = 2 * NT;

    // ---- prologue: load A panel (chunk group 0 together with B chunk 0) ----
#pragma unroll
    for (int u = 0; u < 24; u++) {
        int idx = tid + 256 * u;            // 6144 cp16 total
        int r = idx / 48, q = idx - r * 48;
        cp16(smb + (r * ASTRIDE + q * 4) * 4, A + (bm + r) * KTOT + q * 4);
    }
    // B chunk loader lambda-ish macro
#define LOAD_B(cidx) do {                                                     \
        int _c = (cidx);                                                      \
        int _bn = (_c >> 1) * GBN, _h = (_c & 1) * KH;                        \
        uint32_t _dst = smb + (A_FL + (_c % 3) * B_FL) * 4;                   \
        _Pragma("unroll")                                                     \
        for (int u = 0; u < 6; u++) {                                         \
            int idx = tid + 256 * u;                                          \
            int r = idx / 24, q = idx - r * 24;                               \
            cp16(_dst + (r * BSTRIDE + q * 4) * 4,                            \
                 Wt + (size_t)(_bn + r) * KTOT + _h + q * 4);                 \
        }                                                                     \
    } while (0)

    LOAD_B(0);
    CP_COMMIT();
    LOAD_B(1);
    CP_COMMIT();

    float acc[2][4][4];
#pragma unroll
    for (int mt = 0; mt < 2; mt++)
#pragma unroll
        for (int nt = 0; nt < 4; nt++)
#pragma unroll
            for (int r = 0; r < 4; r++) acc[mt][nt][r] = 0.f;

    const float* arow0 = Asm + (wm * 32 + gp) * ASTRIDE + 2 * tg;
    const float* brow0 = Bsm + (wn * 32 + gp) * BSTRIDE + 2 * tg;

#pragma unroll 1
    for (int c = 0; c < NCHUNK; c++) {
        if (c < NCHUNK - 2) { CP_WAIT(1); } else { CP_WAIT(0); }
        __syncthreads();

        int h = (c & 1) * KH;
        const float* as = arow0 + h;
        const float* bs = brow0 + (c % 3) * B_FL;

#pragma unroll
        for (int g = 0; g < 12; g++) {
            uint32_t a[2][4], b[4][2];
#pragma unroll
            for (int mt = 0; mt < 2; mt++) {
                const float* p = as + mt * 16 * ASTRIDE + g * 8;
                float2 v0 = *(const float2*)p;                    // k = tg, tg+4
                float2 v1 = *(const float2*)(p + 8 * ASTRIDE);
                a[mt][0] = __float_as_uint(v0.x);
                a[mt][2] = __float_as_uint(v0.y);
                a[mt][1] = __float_as_uint(v1.x);
                a[mt][3] = __float_as_uint(v1.y);
            }
#pragma unroll
            for (int nt = 0; nt < 4; nt++) {
                const float* p = bs + nt * 8 * BSTRIDE + g * 8;
                float2 v = *(const float2*)p;
                b[nt][0] = __float_as_uint(v.x);
                b[nt][1] = __float_as_uint(v.y);
            }
#pragma unroll
            for (int mt = 0; mt < 2; mt++)
#pragma unroll
                for (int nt = 0; nt < 4; nt++)
                    mma_m16n8k8(acc[mt][nt], a[mt], b[nt]);
        }

        // epilogue after second half of each n-tile
        if (c & 1) {
            int bn = (c >> 1) * GBN;
#pragma unroll
            for (int mt = 0; mt < 2; mt++) {
                int row = (int)bm + wm * 32 + mt * 16 + gp;
#pragma unroll
                for (int nt = 0; nt < 4; nt++) {
                    int col = bn + wn * 32 + nt * 8 + tg * 2;
                    float b0 = bias[col], b1 = bias[col + 1];
                    float2 v0 = make_float2(acc[mt][nt][0] + b0, acc[mt][nt][1] + b1);
                    float2 v1 = make_float2(acc[mt][nt][2] + b0, acc[mt][nt][3] + b1);
                    *(float2*)(C + (size_t)row * Ntot + col) = v0;
                    *(float2*)(C + (size_t)(row + 8) * Ntot + col) = v1;
                    acc[mt][nt][0] = 0.f; acc[mt][nt][1] = 0.f;
                    acc[mt][nt][2] = 0.f; acc[mt][nt][3] = 0.f;
                }
            }
        }

        // prefetch chunk c+2 (buffer (c+2)%3 was last read at chunk c-1)
        if (c + 2 < NCHUNK) {
            LOAD_B(c + 2);
            CP_COMMIT();
        } else {
            CP_COMMIT();
        }
    }
#undef LOAD_B
}

// ─────────────── attention: single-pass f32x2 (R4 design) ───────────────
__global__ void __launch_bounds__(64)
k_attn(const float* __restrict__ qkv, float* __restrict__ attn,
       const float* __restrict__ rel_pos) {
    int blk = blockIdx.x;
    int head = blk % NHEAD;
    int win = blk / NHEAD;
    int base = win * PPp;
    int tid = threadIdx.x;

    __shared__ __align__(16) float qs[PPp * HDIM];
    __shared__ __align__(16) float ks[PPp * HDIM];
    __shared__ __align__(16) float vs[PPp * HDIM];
    __shared__ float sb[169];

    const size_t rowb = (size_t)base * 576;
    int toff = head * HDIM;
    for (int idx = tid; idx < PPp * 8; idx += 64) {
        int r = idx >> 3, d4 = (idx & 7) * 4;
        size_t g = rowb + (size_t)r * 576 + toff + d4;
        *(float4*)&qs[r * HDIM + d4] = *(const float4*)&qkv[g];
        *(float4*)&ks[r * HDIM + d4] = *(const float4*)&qkv[g + 192];
        *(float4*)&vs[r * HDIM + d4] = *(const float4*)&qkv[g + 384];
    }
    for (int idx = tid; idx < 169; idx += 64) sb[idx] = rel_pos[head * 169 + idx];
    __syncthreads();

    int i = tid;
    if (i >= PPp) return;

    u64t q2[16];
    const u64t* qp = (const u64t*)(qs + i * HDIM);
#pragma unroll
    for (int t = 0; t < 16; t++) q2[t] = qp[t];

    int ii = i / 7, ij = i - (i / 7) * 7;
    const float scale = 0.17677669529663687f;
    float sim[PPp];
#pragma unroll
    for (int j1 = 0; j1 < 7; j1++) {
        int ri = (ii - j1 + 6) * 13 + ij + 6;
#pragma unroll
        for (int j2 = 0; j2 < 7; j2++) {
            int j = j1 * 7 + j2;
            const u64t* kp = (const u64t*)(ks + j * HDIM);
            u64t acc2 = 0ull;
#pragma unroll
            for (int t = 0; t < 16; t++) acc2 = fma2(q2[t], kp[t], acc2);
            sim[j] = (__uint_as_float((uint32_t)acc2) +
                      __uint_as_float((uint32_t)(acc2 >> 32))) * scale + sb[ri - j2];
        }
    }
    float mx = sim[0];
#pragma unroll
    for (int j = 1; j < PPp; j++) mx = fmaxf(mx, sim[j]);
    float sum = 0.f;
#pragma unroll
    for (int j = 0; j < PPp; j++) {
        sim[j] = __expf(sim[j] - mx);
        sum += sim[j];
    }
    float inv = 1.f / sum;

    u64t o2[16];
#pragma unroll
    for (int t = 0; t < 16; t++) o2[t] = 0ull;
#pragma unroll
    for (int j = 0; j < PPp; j++) {
        u64t p2;
        uint32_t pb = __float_as_uint(sim[j]);
        asm("mov.b64 %0, {%1, %1};" : "=l"(p2) : "r"(pb));
        const u64t* vp = (const u64t*)(vs + j * HDIM);
#pragma unroll
        for (int t = 0; t < 16; t++) o2[t] = fma2(p2, vp[t], o2[t]);
    }

    // direct store: tf32-rounded, k-permuted pairs (d, d+4) -> pos 2d
    float od[HDIM];
#pragma unroll
    for (int t = 0; t < 16; t++) {
        od[2 * t]     = __uint_as_float((uint32_t)o2[t]) * inv;
        od[2 * t + 1] = __uint_as_float((uint32_t)(o2[t] >> 32)) * inv;
    }
    float* op = attn + (size_t)(base + i) * Cch + toff;
#pragma unroll
    for (int g = 0; g < 4; g++)
#pragma unroll
        for (int m = 0; m < 4; m++) {
            float2 v = make_float2(f2tf_f(od[g * 8 + m]), f2tf_f(od[g * 8 + m + 4]));
            *(float2*)(op + g * 8 + 2 * m) = v;
        }
}

// ───────────────────────── launch ─────────────────────────
extern "C" void kernel_launch(void* const* d_in, const int* in_sizes, int n_in,
                              void* d_out, int out_size) {
    const float* x       = (const float*)d_in[0];
    const float* w_qkv   = (const float*)d_in[1];
    const float* b_qkv   = (const float*)d_in[2];
    const float* rel_pos = (const float*)d_in[3];
    const float* w_out   = (const float*)d_in[4];
    const float* b_out   = (const float*)d_in[5];
    float* out = (float*)d_out;

    float *p_xw, *p_qkv, *p_attn, *p_out2, *p_wqkv, *p_wout;
    cudaGetSymbolAddress((void**)&p_xw, g_xw);
    cudaGetSymbolAddress((void**)&p_qkv, g_qkv);
    cudaGetSymbolAddress((void**)&p_attn, g_attn);
    cudaGetSymbolAddress((void**)&p_out2, g_out2);
    cudaGetSymbolAddress((void**)&p_wqkv, g_wqkv);
    cudaGetSymbolAddress((void**)&p_wout, g_wout);

    cudaFuncSetAttribute(k_gemm_mma, cudaFuncAttributeMaxDynamicSharedMemorySize, GEMM_SMEM);

    k_round<<<(576 * 192 + 255) / 256, 256>>>(w_qkv, p_wqkv, 576 * 192);
    k_round<<<(192 * 192 + 255) / 256, 256>>>(w_out, p_wout, 192 * 192);

    dim3 tb(32, 8);
    dim3 tg(HWSZ / 32, Cch / 32, Bsz);
    k_gather<<<tg, tb>>>(x, p_xw);
    k_gemm_mma<<<Mrows / GBM, 256, GEMM_SMEM>>>(p_xw, p_wqkv, b_qkv, p_qkv, 576, 9);
    k_attn<<<(Mrows / PPp) * NHEAD, 64>>>(p_qkv, p_attn, rel_pos);
    k_gemm_mma<<<Mrows / GBM, 256, GEMM_SMEM>>>(p_attn, p_wout, b_out, p_out2, 192, 3);
    k_scatter<<<tg, tb>>>(p_out2, out);
}